// round 4
// baseline (speedup 1.0000x reference)
#include <cuda_runtime.h>
#include <cuda_fp16.h>
#include <cstdint>

#define DEVINL __device__ __forceinline__

namespace {
constexpr int Sn  = 1024;
constexpr int Vn  = 300;
constexpr int PRE = 300;
constexpr int FLG = 16;
constexpr int KQn = 316;
constexpr int RD  = 200;
constexpr int BSn = 32768;            // B*S

// tiling: block 128x112, 4 warps (2x2), warp tile 64x56, K chunk 32
constexpr int BM = 128, BN = 112, STR = 48;   // smem row stride in halves
constexpr int ASZ = BM * STR;                 // 6144 halves per split
constexpr int BSZ = BN * STR;                 // 5376
constexpr int AHo = 0, ALo = ASZ, BHo = 2 * ASZ, BLo = 2 * ASZ + BSZ;
constexpr int STAGE_H = 2 * ASZ + 2 * BSZ;    // 23040 halves
constexpr int SMEM_BYTES = 2 * STAGE_H * 2;   // 92160

constexpr int NC1 = 10;   // GEMM1 K chunks (K=316 -> 320)
constexpr int NC2 = 7;    // GEMM2 K chunks (K=200 -> 224)
constexpr int PW  = 224;  // proj padded width
}

// fp16 hi/lo global scratch (allocation-free rule)
__device__ __half g_ph[(size_t)BSn * PW];
__device__ __half g_pl[(size_t)BSn * PW];
__device__ __half g_mh[224 * 320];
__device__ __half g_ml[224 * 320];

// ---------------------------------------------------------------------------
DEVINL uint32_t smem_u32(const void* p) {
    uint32_t a;
    asm("{ .reg .u64 t; cvta.to.shared.u64 t, %1; cvt.u32.u64 %0, t; }"
        : "=r"(a) : "l"(p));
    return a;
}
DEVINL void cp16(uint32_t dst, const void* src) {
    asm volatile("cp.async.cg.shared.global [%0], [%1], 16;"
                 :: "r"(dst), "l"(src) : "memory");
}
DEVINL void cp_commit() { asm volatile("cp.async.commit_group;" ::: "memory"); }
DEVINL void cp_wait0()  { asm volatile("cp.async.wait_group 0;" ::: "memory"); }

DEVINL void ldsm4(uint32_t a, uint32_t& r0, uint32_t& r1, uint32_t& r2, uint32_t& r3) {
    asm volatile("ldmatrix.sync.aligned.m8n8.x4.shared.b16 {%0,%1,%2,%3}, [%4];"
                 : "=r"(r0), "=r"(r1), "=r"(r2), "=r"(r3) : "r"(a));
}
DEVINL void ldsm2(uint32_t a, uint32_t& r0, uint32_t& r1) {
    asm volatile("ldmatrix.sync.aligned.m8n8.x2.shared.b16 {%0,%1}, [%2];"
                 : "=r"(r0), "=r"(r1) : "r"(a));
}
DEVINL void mma16816(float* c, const uint32_t* a, uint32_t b0, uint32_t b1) {
    asm volatile(
        "mma.sync.aligned.m16n8k16.row.col.f32.f16.f16.f32 "
        "{%0,%1,%2,%3}, {%4,%5,%6,%7}, {%8,%9}, {%0,%1,%2,%3};"
        : "+f"(c[0]), "+f"(c[1]), "+f"(c[2]), "+f"(c[3])
        : "r"(a[0]), "r"(a[1]), "r"(a[2]), "r"(a[3]), "r"(b0), "r"(b1));
}

// swizzle: flip 16B unit on row parity-of-4 (conflict-free ldmatrix at stride 96B)
DEVINL uint32_t swz(uint32_t byteoff, int row) { return byteoff ^ ((row & 4) << 2); }

DEVINL uint32_t packh(__half x, __half y) {
    return ((uint32_t)__half_as_ushort(y) << 16) | (uint32_t)__half_as_ushort(x);
}
DEVINL void split2h(float x, float y, uint32_t& hi, uint32_t& lo) {
    __half hx = __float2half_rn(x), hy = __float2half_rn(y);
    __half lx = __float2half_rn(x - __half2float(hx));
    __half ly = __float2half_rn(y - __half2float(hy));
    hi = packh(hx, hy);
    lo = packh(lx, ly);
}
DEVINL void store_split_pair(__half* hp, __half* lp, size_t off, float x, float y) {
    uint32_t hi, lo;
    split2h(x, y, hi, lo);
    *reinterpret_cast<uint32_t*>(hp + off) = hi;
    *reinterpret_cast<uint32_t*>(lp + off) = lo;
}
DEVINL void sts2(uint32_t addr, uint32_t a, uint32_t b) {
    asm volatile("st.shared.v2.u32 [%0], {%1,%2};" :: "r"(addr), "r"(a), "r"(b) : "memory");
}

// ---------------------------------------------------------------------------
// compute one K-chunk (2 x k16 steps), warp tile 64x56, 3-term fp16 split
// ---------------------------------------------------------------------------
DEVINL void compute_chunk(uint32_t sb, int lane, int wm, int wn, float c[4][7][4]) {
    const int lr = lane & 15;
#pragma unroll
    for (int s = 0; s < 2; ++s) {
        uint32_t ah[4][4], al[4][4];
#pragma unroll
        for (int mi = 0; mi < 4; ++mi) {
            const int row = wm * 64 + mi * 16 + lr;
            const int col = s * 16 + (lane >> 4) * 8;
            const uint32_t off = swz((uint32_t)(row * STR + col) * 2, row);
            ldsm4(sb + AHo * 2 + off, ah[mi][0], ah[mi][1], ah[mi][2], ah[mi][3]);
            ldsm4(sb + ALo * 2 + off, al[mi][0], al[mi][1], al[mi][2], al[mi][3]);
        }
        // B: 3 ni-pairs via ldsm4 + 1 single via ldsm2
#pragma unroll
        for (int nip = 0; nip < 3; ++nip) {
            const int g = lane >> 3;
            const int brow = wn * 56 + nip * 16 + (g & 1) * 8 + (lane & 7);
            const int bcol = s * 16 + (g >> 1) * 8;
            const uint32_t boff = swz((uint32_t)(brow * STR + bcol) * 2, brow);
            uint32_t bh[4], bl[4];
            ldsm4(sb + BHo * 2 + boff, bh[0], bh[1], bh[2], bh[3]);
            ldsm4(sb + BLo * 2 + boff, bl[0], bl[1], bl[2], bl[3]);
            // matrices: [0]=ni_even k0-7, [1]=ni_odd k0-7, [2]=ni_even k8-15, [3]=ni_odd k8-15
#pragma unroll
            for (int mi = 0; mi < 4; ++mi) {
                mma16816(c[mi][2 * nip],     ah[mi], bh[0], bh[2]);
                mma16816(c[mi][2 * nip],     ah[mi], bl[0], bl[2]);
                mma16816(c[mi][2 * nip],     al[mi], bh[0], bh[2]);
                mma16816(c[mi][2 * nip + 1], ah[mi], bh[1], bh[3]);
                mma16816(c[mi][2 * nip + 1], ah[mi], bl[1], bl[3]);
                mma16816(c[mi][2 * nip + 1], al[mi], bh[1], bh[3]);
            }
        }
        {
            const int brow = wn * 56 + 48 + (lr & 7);
            const int bcol = s * 16 + ((lr >> 3) & 1) * 8;
            const uint32_t boff = swz((uint32_t)(brow * STR + bcol) * 2, brow);
            uint32_t bh0, bh1, bl0, bl1;
            ldsm2(sb + BHo * 2 + boff, bh0, bh1);
            ldsm2(sb + BLo * 2 + boff, bl0, bl1);
#pragma unroll
            for (int mi = 0; mi < 4; ++mi) {
                mma16816(c[mi][6], ah[mi], bh0, bh1);
                mma16816(c[mi][6], ah[mi], bl0, bl1);
                mma16816(c[mi][6], al[mi], bh0, bh1);
            }
        }
    }
}

// ===========================================================================
// prep: split/pad matrix (transposed) into fp16 hi/lo scratch
// ===========================================================================
__global__ void prep_mat(const float* __restrict__ mat) {
    const int idx = blockIdx.x * 256 + threadIdx.x;    // 224*80 = 17920
    if (idx >= 224 * 80) return;
    const int n = idx / 80, k4 = (idx % 80) * 4;
#pragma unroll
    for (int i = 0; i < 4; ++i) {
        const int k = k4 + i;
        float v = 0.f;
        if (n < RD && k < KQn) v = mat[(size_t)k * RD + n];
        __half h = __float2half_rn(v);
        __half l = __float2half_rn(v - __half2float(h));
        g_mh[n * 320 + k] = h;
        g_ml[n * 320 + k] = l;
    }
}

// ===========================================================================
// GEMM1: proj(hi/lo f16)[BS,224] = concat(pre,wid)[BS,316] @ mat[316,200]
// ===========================================================================
__global__ __launch_bounds__(128, 2) void gemm1(
    const float* __restrict__ pre,
    const float* __restrict__ wid)
{
    extern __shared__ __align__(16) char smraw[];
    const uint32_t sb0 = smem_u32(smraw);
    const int t = threadIdx.x, lane = t & 31, warp = t >> 5;
    const int wm = warp >> 1, wn = warp & 1;
    const int m0 = blockIdx.x * BM;
    const int n0 = blockIdx.y * BN;

    float c[4][7][4] = {};
    float4 ar[8];

    auto ldA = [&](int ch) {
#pragma unroll
        for (int j = 0; j < 8; ++j) {
            const int idx = t + 128 * j;
            const int row = idx >> 3, c4 = idx & 7;
            const int kg = ch * 32 + c4 * 4;
            const size_t rg = (size_t)(m0 + row);
            float4 v = make_float4(0.f, 0.f, 0.f, 0.f);
            if (kg < PRE)      v = *(const float4*)(pre + rg * PRE + kg);
            else if (kg < KQn) v = *(const float4*)(wid + rg * FLG + (kg - PRE));
            ar[j] = v;
        }
    };
    auto stA = [&](uint32_t sb) {
#pragma unroll
        for (int j = 0; j < 8; ++j) {
            const int idx = t + 128 * j;
            const int row = idx >> 3, c4 = idx & 7;
            uint32_t h0, l0, h1, l1;
            split2h(ar[j].x, ar[j].y, h0, l0);
            split2h(ar[j].z, ar[j].w, h1, l1);
            const uint32_t off = swz((uint32_t)(row * 96 + c4 * 8), row);
            sts2(sb + AHo * 2 + off, h0, h1);
            sts2(sb + ALo * 2 + off, l0, l1);
        }
    };
    auto issueB = [&](int ch, uint32_t sb) {
#pragma unroll
        for (int j = 0; j < 7; ++j) {
            const int idx = t + 128 * j;   // 896 total
            const int sp = idx / 448, rem = idx % 448;
            const int row = rem >> 2, c8 = rem & 3;
            const __half* src = (sp ? g_ml : g_mh)
                              + (size_t)(n0 + row) * 320 + ch * 32 + c8 * 8;
            const uint32_t off = (sp ? BLo : BHo) * 2
                               + swz((uint32_t)(row * 96 + c8 * 16), row);
            cp16(sb + off, src);
        }
    };

    ldA(0);
    issueB(0, sb0);
    cp_commit();
    stA(sb0);
    cp_wait0();
    __syncthreads();

    for (int ch = 0; ch < NC1; ++ch) {
        const uint32_t cur = sb0 + (uint32_t)(ch & 1) * STAGE_H * 2;
        const uint32_t nxt = sb0 + (uint32_t)((ch + 1) & 1) * STAGE_H * 2;
        if (ch + 1 < NC1) { ldA(ch + 1); issueB(ch + 1, nxt); cp_commit(); }
        compute_chunk(cur, lane, wm, wn, c);
        if (ch + 1 < NC1) { stA(nxt); cp_wait0(); }
        __syncthreads();
    }

    // epilogue: split fp32 -> proj hi/lo f16 (cols >= 200 are exact zeros)
#pragma unroll
    for (int mi = 0; mi < 4; ++mi)
#pragma unroll
    for (int ni = 0; ni < 7; ++ni) {
        const int r0   = m0 + wm * 64 + mi * 16 + (lane >> 2);
        const int colg = n0 + wn * 56 + ni * 8 + (lane & 3) * 2;
        store_split_pair(g_ph, g_pl, (size_t)r0 * PW + colg,
                         c[mi][ni][0], c[mi][ni][1]);
        store_split_pair(g_ph, g_pl, (size_t)(r0 + 8) * PW + colg,
                         c[mi][ni][2], c[mi][ni][3]);
    }
}

// ===========================================================================
// GEMM2: out[r, v] = proj[r,:] . roles[b(r), v, :], col v==1 zeroed
// roles loaded fp32 directly, split in-loader (no prep round-trip)
// ===========================================================================
__global__ __launch_bounds__(128, 2) void gemm2(
    const float* __restrict__ roles,
    float* __restrict__ out)
{
    extern __shared__ __align__(16) char smraw[];
    const uint32_t sb0 = smem_u32(smraw);
    const int t = threadIdx.x, lane = t & 31, warp = t >> 5;
    const int wm = warp >> 1, wn = warp & 1;
    const int m0 = blockIdx.x * BM;
    const int n0 = blockIdx.y * BN;
    const int b  = blockIdx.x >> 3;           // 8 M-tiles per batch

    float c[4][7][4] = {};
    float4 br[7];
    const float* Rb = roles + (size_t)b * Vn * RD;

    auto issueA = [&](int ch, uint32_t sb) {
        const int k0 = ch * 32;
#pragma unroll
        for (int j = 0; j < 8; ++j) {
            const int idx = t + 128 * j;   // 1024 total
            const int sp = idx >> 9, rem = idx & 511;
            const int row = rem >> 2, c8 = rem & 3;
            const __half* src = (sp ? g_pl : g_ph)
                              + (size_t)(m0 + row) * PW + k0 + c8 * 8;
            const uint32_t off = (sp ? ALo : AHo) * 2
                               + swz((uint32_t)(row * 96 + c8 * 16), row);
            cp16(sb + off, src);
        }
    };
    auto ldB = [&](int ch) {
#pragma unroll
        for (int j = 0; j < 7; ++j) {
            const int idx = t + 128 * j;   // 896 total
            const int row = idx >> 3, c4 = idx & 7;
            const int kg = ch * 32 + c4 * 4;
            const int vg = n0 + row;
            float4 v = make_float4(0.f, 0.f, 0.f, 0.f);
            if (vg < Vn && kg < RD)
                v = *(const float4*)(Rb + (size_t)vg * RD + kg);
            br[j] = v;
        }
    };
    auto stB = [&](uint32_t sb) {
#pragma unroll
        for (int j = 0; j < 7; ++j) {
            const int idx = t + 128 * j;
            const int row = idx >> 3, c4 = idx & 7;
            uint32_t h0, l0, h1, l1;
            split2h(br[j].x, br[j].y, h0, l0);
            split2h(br[j].z, br[j].w, h1, l1);
            const uint32_t off = swz((uint32_t)(row * 96 + c4 * 8), row);
            sts2(sb + BHo * 2 + off, h0, h1);
            sts2(sb + BLo * 2 + off, l0, l1);
        }
    };

    ldB(0);
    issueA(0, sb0);
    cp_commit();
    stB(sb0);
    cp_wait0();
    __syncthreads();

    for (int ch = 0; ch < NC2; ++ch) {
        const uint32_t cur = sb0 + (uint32_t)(ch & 1) * STAGE_H * 2;
        const uint32_t nxt = sb0 + (uint32_t)((ch + 1) & 1) * STAGE_H * 2;
        if (ch + 1 < NC2) { ldB(ch + 1); issueA(ch + 1, nxt); cp_commit(); }
        compute_chunk(cur, lane, wm, wn, c);
        if (ch + 1 < NC2) { stB(nxt); cp_wait0(); }
        __syncthreads();
    }

    // epilogue: fp32 stores, zero global column 1
#pragma unroll
    for (int mi = 0; mi < 4; ++mi)
#pragma unroll
    for (int ni = 0; ni < 7; ++ni) {
        const int r0   = m0 + wm * 64 + mi * 16 + (lane >> 2);
        const int colg = n0 + wn * 56 + ni * 8 + (lane & 3) * 2;
        if (colg < Vn) {
            float a0 = c[mi][ni][0], a1 = c[mi][ni][1];
            float a2 = c[mi][ni][2], a3 = c[mi][ni][3];
            if (colg == 0) { a1 = 0.f; a3 = 0.f; }
            *(float2*)(out + (size_t)r0 * Vn + colg)       = make_float2(a0, a1);
            *(float2*)(out + (size_t)(r0 + 8) * Vn + colg) = make_float2(a2, a3);
        }
    }
}

// ===========================================================================
// kernel_launch  (inputs: role_vectors, pretrained_emb, word_id_emb, matrix, seq_len)
// ===========================================================================
extern "C" void kernel_launch(void* const* d_in, const int* in_sizes, int n_in,
                              void* d_out, int out_size)
{
    const float* roles = (const float*)d_in[0];
    const float* pre   = (const float*)d_in[1];
    const float* wid   = (const float*)d_in[2];
    const float* mat   = (const float*)d_in[3];

    cudaFuncSetAttribute(gemm1, cudaFuncAttributeMaxDynamicSharedMemorySize, SMEM_BYTES);
    cudaFuncSetAttribute(gemm2, cudaFuncAttributeMaxDynamicSharedMemorySize, SMEM_BYTES);

    prep_mat<<<(224 * 80 + 255) / 256, 256>>>(mat);
    gemm1<<<dim3(BSn / BM, 2), 128, SMEM_BYTES>>>(pre, wid);
    gemm2<<<dim3(BSn / BM, 3), 128, SMEM_BYTES>>>(roles, (float*)d_out);
}

// round 5
// speedup vs baseline: 1.0726x; 1.0726x over previous
#include <cuda_runtime.h>
#include <cuda_fp16.h>
#include <cstdint>

#define DEVINL __device__ __forceinline__

namespace {
constexpr int Sn  = 1024;
constexpr int Vn  = 300;
constexpr int PRE = 300;
constexpr int FLG = 16;
constexpr int KQn = 316;
constexpr int RD  = 200;
constexpr int BSn = 32768;            // B*S

// tiling: block 128x112, 8 warps (4x2), warp tile 32x56, K chunk 32
constexpr int BM = 128, BN = 112, STR = 48;   // smem row stride in halves
constexpr int ASZ = BM * STR;                 // 6144 halves per split
constexpr int BSZ = BN * STR;                 // 5376
constexpr int AHo = 0, ALo = ASZ, BHo = 2 * ASZ, BLo = 2 * ASZ + BSZ;
constexpr int STAGE_H = 2 * ASZ + 2 * BSZ;    // 23040 halves
constexpr int SMEM_BYTES = 2 * STAGE_H * 2;   // 92160

constexpr int NC1 = 10;   // GEMM1 K chunks (K=316 -> 320)
constexpr int NC2 = 7;    // GEMM2 K chunks (K=200 -> 224)
constexpr int PW  = 224;  // proj padded width (k)
constexpr int RW  = 224;  // roles padded k
constexpr int RV  = 336;  // roles padded v

constexpr int PREP_MAT_N   = 224 * 80;               // 17920
constexpr int PREP_ROLE_N  = 32 * RV * (RW / 4);     // 602112
constexpr int PREP_TOTAL   = PREP_MAT_N + PREP_ROLE_N;
}

// fp16 hi/lo global scratch (allocation-free rule)
__device__ __half g_ph[(size_t)BSn * PW];
__device__ __half g_pl[(size_t)BSn * PW];
__device__ __half g_mh[224 * 320];
__device__ __half g_ml[224 * 320];
__device__ __half g_rh[(size_t)32 * RV * RW];
__device__ __half g_rl[(size_t)32 * RV * RW];

// ---------------------------------------------------------------------------
DEVINL uint32_t smem_u32(const void* p) {
    uint32_t a;
    asm("{ .reg .u64 t; cvta.to.shared.u64 t, %1; cvt.u32.u64 %0, t; }"
        : "=r"(a) : "l"(p));
    return a;
}
DEVINL void cp16(uint32_t dst, const void* src) {
    asm volatile("cp.async.cg.shared.global [%0], [%1], 16;"
                 :: "r"(dst), "l"(src) : "memory");
}
DEVINL void cp_commit() { asm volatile("cp.async.commit_group;" ::: "memory"); }
DEVINL void cp_wait0()  { asm volatile("cp.async.wait_group 0;" ::: "memory"); }

DEVINL void ldsm4(uint32_t a, uint32_t& r0, uint32_t& r1, uint32_t& r2, uint32_t& r3) {
    asm volatile("ldmatrix.sync.aligned.m8n8.x4.shared.b16 {%0,%1,%2,%3}, [%4];"
                 : "=r"(r0), "=r"(r1), "=r"(r2), "=r"(r3) : "r"(a));
}
DEVINL void ldsm2(uint32_t a, uint32_t& r0, uint32_t& r1) {
    asm volatile("ldmatrix.sync.aligned.m8n8.x2.shared.b16 {%0,%1}, [%2];"
                 : "=r"(r0), "=r"(r1) : "r"(a));
}
DEVINL void mma16816(float* c, const uint32_t* a, uint32_t b0, uint32_t b1) {
    asm volatile(
        "mma.sync.aligned.m16n8k16.row.col.f32.f16.f16.f32 "
        "{%0,%1,%2,%3}, {%4,%5,%6,%7}, {%8,%9}, {%0,%1,%2,%3};"
        : "+f"(c[0]), "+f"(c[1]), "+f"(c[2]), "+f"(c[3])
        : "r"(a[0]), "r"(a[1]), "r"(a[2]), "r"(a[3]), "r"(b0), "r"(b1));
}

// swizzle: flip 16B unit on row parity-of-4 (conflict-free ldmatrix at stride 96B)
DEVINL uint32_t swz(uint32_t byteoff, int row) { return byteoff ^ ((row & 4) << 2); }

DEVINL uint32_t packh(__half x, __half y) {
    return ((uint32_t)__half_as_ushort(y) << 16) | (uint32_t)__half_as_ushort(x);
}
DEVINL void split2h(float x, float y, uint32_t& hi, uint32_t& lo) {
    __half hx = __float2half_rn(x), hy = __float2half_rn(y);
    __half lx = __float2half_rn(x - __half2float(hx));
    __half ly = __float2half_rn(y - __half2float(hy));
    hi = packh(hx, hy);
    lo = packh(lx, ly);
}
DEVINL void store_split_pair(__half* hp, __half* lp, size_t off, float x, float y) {
    uint32_t hi, lo;
    split2h(x, y, hi, lo);
    *reinterpret_cast<uint32_t*>(hp + off) = hi;
    *reinterpret_cast<uint32_t*>(lp + off) = lo;
}
DEVINL void sts2(uint32_t addr, uint32_t a, uint32_t b) {
    asm volatile("st.shared.v2.u32 [%0], {%1,%2};" :: "r"(addr), "r"(a), "r"(b) : "memory");
}

// ---------------------------------------------------------------------------
// compute one K-chunk (2 x k16 steps), warp tile 32x56, 3-term fp16 split
// B frags: 3 ni-pairs via ldsm4 + 1 single via ldsm2
// ---------------------------------------------------------------------------
DEVINL void compute_chunk(uint32_t sb, int lane, int wm, int wn, float c[2][7][4]) {
    const int lr = lane & 15;
#pragma unroll
    for (int s = 0; s < 2; ++s) {
        uint32_t ah[2][4], al[2][4];
#pragma unroll
        for (int mi = 0; mi < 2; ++mi) {
            const int row = wm * 32 + mi * 16 + lr;
            const int col = s * 16 + (lane >> 4) * 8;
            const uint32_t off = swz((uint32_t)(row * STR + col) * 2, row);
            ldsm4(sb + AHo * 2 + off, ah[mi][0], ah[mi][1], ah[mi][2], ah[mi][3]);
            ldsm4(sb + ALo * 2 + off, al[mi][0], al[mi][1], al[mi][2], al[mi][3]);
        }
#pragma unroll
        for (int nip = 0; nip < 3; ++nip) {
            const int g = lane >> 3;
            const int brow = wn * 56 + nip * 16 + (g & 1) * 8 + (lane & 7);
            const int bcol = s * 16 + (g >> 1) * 8;
            const uint32_t boff = swz((uint32_t)(brow * STR + bcol) * 2, brow);
            uint32_t bh[4], bl[4];
            ldsm4(sb + BHo * 2 + boff, bh[0], bh[1], bh[2], bh[3]);
            ldsm4(sb + BLo * 2 + boff, bl[0], bl[1], bl[2], bl[3]);
            // [0]=ni_even k0-7, [1]=ni_odd k0-7, [2]=ni_even k8-15, [3]=ni_odd k8-15
#pragma unroll
            for (int mi = 0; mi < 2; ++mi) {
                mma16816(c[mi][2 * nip],     ah[mi], bh[0], bh[2]);
                mma16816(c[mi][2 * nip],     ah[mi], bl[0], bl[2]);
                mma16816(c[mi][2 * nip],     al[mi], bh[0], bh[2]);
                mma16816(c[mi][2 * nip + 1], ah[mi], bh[1], bh[3]);
                mma16816(c[mi][2 * nip + 1], ah[mi], bl[1], bl[3]);
                mma16816(c[mi][2 * nip + 1], al[mi], bh[1], bh[3]);
            }
        }
        {
            const int brow = wn * 56 + 48 + (lr & 7);
            const int bcol = s * 16 + ((lr >> 3) & 1) * 8;
            const uint32_t boff = swz((uint32_t)(brow * STR + bcol) * 2, brow);
            uint32_t bh0, bh1, bl0, bl1;
            ldsm2(sb + BHo * 2 + boff, bh0, bh1);
            ldsm2(sb + BLo * 2 + boff, bl0, bl1);
#pragma unroll
            for (int mi = 0; mi < 2; ++mi) {
                mma16816(c[mi][6], ah[mi], bh0, bh1);
                mma16816(c[mi][6], ah[mi], bl0, bl1);
                mma16816(c[mi][6], al[mi], bh0, bh1);
            }
        }
    }
}

// ===========================================================================
// prep (merged): split/pad matrix (transposed) and roles into fp16 hi/lo
// ===========================================================================
__global__ void prep_all(const float* __restrict__ mat,
                         const float* __restrict__ roles) {
    const int idx = blockIdx.x * 256 + threadIdx.x;
    if (idx < PREP_MAT_N) {
        const int n = idx / 80, k4 = (idx % 80) * 4;
#pragma unroll
        for (int i = 0; i < 4; ++i) {
            const int k = k4 + i;
            float v = 0.f;
            if (n < RD && k < KQn) v = mat[(size_t)k * RD + n];
            __half h = __float2half_rn(v);
            __half l = __float2half_rn(v - __half2float(h));
            g_mh[n * 320 + k] = h;
            g_ml[n * 320 + k] = l;
        }
    } else if (idx < PREP_TOTAL) {
        const int r0 = idx - PREP_MAT_N;
        const int b  = r0 / (RV * (RW / 4));
        const int r  = r0 % (RV * (RW / 4));
        const int v  = r / (RW / 4);
        const int k  = (r % (RW / 4)) * 4;
        uint32_t h0 = 0, l0 = 0, h1 = 0, l1 = 0;
        if (v < Vn && k < RD) {
            const float4 f = *(const float4*)(roles + ((size_t)b * Vn + v) * RD + k);
            split2h(f.x, f.y, h0, l0);
            split2h(f.z, f.w, h1, l1);
        }
        const size_t off = (size_t)b * RV * RW + (size_t)v * RW + k;
        *reinterpret_cast<uint2*>(g_rh + off) = make_uint2(h0, h1);
        *reinterpret_cast<uint2*>(g_rl + off) = make_uint2(l0, l1);
    }
}

// ===========================================================================
// GEMM1: proj(hi/lo f16)[BS,224] = concat(pre,wid)[BS,316] @ mat[316,200]
// ===========================================================================
__global__ __launch_bounds__(256, 2) void gemm1(
    const float* __restrict__ pre,
    const float* __restrict__ wid)
{
    extern __shared__ __align__(16) char smraw[];
    const uint32_t sb0 = smem_u32(smraw);
    const int t = threadIdx.x, lane = t & 31, warp = t >> 5;
    const int wm = warp >> 1, wn = warp & 1;
    const int m0 = blockIdx.x * BM;
    const int n0 = blockIdx.y * BN;

    float c[2][7][4] = {};
    float4 ar[4];

    auto ldA = [&](int ch) {
#pragma unroll
        for (int j = 0; j < 4; ++j) {
            const int idx = t + 256 * j;
            const int row = idx >> 3, c4 = idx & 7;
            const int kg = ch * 32 + c4 * 4;
            const size_t rg = (size_t)(m0 + row);
            float4 v = make_float4(0.f, 0.f, 0.f, 0.f);
            if (kg < PRE)      v = *(const float4*)(pre + rg * PRE + kg);
            else if (kg < KQn) v = *(const float4*)(wid + rg * FLG + (kg - PRE));
            ar[j] = v;
        }
    };
    auto stA = [&](uint32_t sb) {
#pragma unroll
        for (int j = 0; j < 4; ++j) {
            const int idx = t + 256 * j;
            const int row = idx >> 3, c4 = idx & 7;
            uint32_t h0, l0, h1, l1;
            split2h(ar[j].x, ar[j].y, h0, l0);
            split2h(ar[j].z, ar[j].w, h1, l1);
            const uint32_t off = swz((uint32_t)(row * 96 + c4 * 8), row);
            sts2(sb + AHo * 2 + off, h0, h1);
            sts2(sb + ALo * 2 + off, l0, l1);
        }
    };
    auto issueB = [&](int ch, uint32_t sb) {
#pragma unroll
        for (int j = 0; j < 4; ++j) {
            const int idx = t + 256 * j;
            if (idx < 896) {
                const int sp = idx / 448, rem = idx % 448;
                const int row = rem >> 2, c8 = rem & 3;
                const __half* src = (sp ? g_ml : g_mh)
                                  + (size_t)(n0 + row) * 320 + ch * 32 + c8 * 8;
                const uint32_t off = (sp ? BLo : BHo) * 2
                                   + swz((uint32_t)(row * 96 + c8 * 16), row);
                cp16(sb + off, src);
            }
        }
    };

    ldA(0);
    issueB(0, sb0);
    cp_commit();
    stA(sb0);
    cp_wait0();
    __syncthreads();

    for (int ch = 0; ch < NC1; ++ch) {
        const uint32_t cur = sb0 + (uint32_t)(ch & 1) * STAGE_H * 2;
        const uint32_t nxt = sb0 + (uint32_t)((ch + 1) & 1) * STAGE_H * 2;
        if (ch + 1 < NC1) { ldA(ch + 1); issueB(ch + 1, nxt); cp_commit(); }
        compute_chunk(cur, lane, wm, wn, c);
        if (ch + 1 < NC1) { stA(nxt); cp_wait0(); }
        __syncthreads();
    }

    // epilogue: split fp32 -> proj hi/lo f16 (cols >= 200 are exact zeros)
#pragma unroll
    for (int mi = 0; mi < 2; ++mi)
#pragma unroll
    for (int ni = 0; ni < 7; ++ni) {
        const int r0   = m0 + wm * 32 + mi * 16 + (lane >> 2);
        const int colg = n0 + wn * 56 + ni * 8 + (lane & 3) * 2;
        store_split_pair(g_ph, g_pl, (size_t)r0 * PW + colg,
                         c[mi][ni][0], c[mi][ni][1]);
        store_split_pair(g_ph, g_pl, (size_t)(r0 + 8) * PW + colg,
                         c[mi][ni][2], c[mi][ni][3]);
    }
}

// ===========================================================================
// GEMM2: out[r, v] = proj[r,:] . roles[b(r), v, :], col v==1 zeroed
// ===========================================================================
__global__ __launch_bounds__(256, 2) void gemm2(float* __restrict__ out)
{
    extern __shared__ __align__(16) char smraw[];
    const uint32_t sb0 = smem_u32(smraw);
    const int t = threadIdx.x, lane = t & 31, warp = t >> 5;
    const int wm = warp >> 1, wn = warp & 1;
    const int m0 = blockIdx.x * BM;
    const int n0 = blockIdx.y * BN;
    const int b  = blockIdx.x >> 3;           // 8 M-tiles per batch

    float c[2][7][4] = {};
    const size_t rbase = (size_t)b * RV * RW;

    auto issue = [&](int ch, uint32_t sb) {
        const int k0 = ch * 32;
#pragma unroll
        for (int j = 0; j < 8; ++j) {
            const int idx = t + 256 * j;
            if (idx < 1024) {                       // A: proj hi/lo
                const int sp = idx >> 9, rem = idx & 511;
                const int row = rem >> 2, c8 = rem & 3;
                const __half* src = (sp ? g_pl : g_ph)
                                  + (size_t)(m0 + row) * PW + k0 + c8 * 8;
                const uint32_t off = (sp ? ALo : AHo) * 2
                                   + swz((uint32_t)(row * 96 + c8 * 16), row);
                cp16(sb + off, src);
            } else if (idx < 1920) {                // B: roles hi/lo
                const int i2 = idx - 1024;
                const int sp = i2 / 448, rem = i2 % 448;
                const int row = rem >> 2, c8 = rem & 3;
                const __half* src = (sp ? g_rl : g_rh)
                                  + rbase + (size_t)(n0 + row) * RW + k0 + c8 * 8;
                const uint32_t off = (sp ? BLo : BHo) * 2
                                   + swz((uint32_t)(row * 96 + c8 * 16), row);
                cp16(sb + off, src);
            }
        }
    };

    issue(0, sb0);
    cp_commit();
    cp_wait0();
    __syncthreads();

    for (int ch = 0; ch < NC2; ++ch) {
        const uint32_t cur = sb0 + (uint32_t)(ch & 1) * STAGE_H * 2;
        const uint32_t nxt = sb0 + (uint32_t)((ch + 1) & 1) * STAGE_H * 2;
        if (ch + 1 < NC2) { issue(ch + 1, nxt); cp_commit(); }
        compute_chunk(cur, lane, wm, wn, c);
        if (ch + 1 < NC2) cp_wait0();
        __syncthreads();
    }

    // epilogue: fp32 stores, zero global column 1
#pragma unroll
    for (int mi = 0; mi < 2; ++mi)
#pragma unroll
    for (int ni = 0; ni < 7; ++ni) {
        const int r0   = m0 + wm * 32 + mi * 16 + (lane >> 2);
        const int colg = n0 + wn * 56 + ni * 8 + (lane & 3) * 2;
        if (colg < Vn) {
            float a0 = c[mi][ni][0], a1 = c[mi][ni][1];
            float a2 = c[mi][ni][2], a3 = c[mi][ni][3];
            if (colg == 0) { a1 = 0.f; a3 = 0.f; }
            *(float2*)(out + (size_t)r0 * Vn + colg)       = make_float2(a0, a1);
            *(float2*)(out + (size_t)(r0 + 8) * Vn + colg) = make_float2(a2, a3);
        }
    }
}

// ===========================================================================
// kernel_launch  (inputs: role_vectors, pretrained_emb, word_id_emb, matrix, seq_len)
// ===========================================================================
extern "C" void kernel_launch(void* const* d_in, const int* in_sizes, int n_in,
                              void* d_out, int out_size)
{
    const float* roles = (const float*)d_in[0];
    const float* pre   = (const float*)d_in[1];
    const float* wid   = (const float*)d_in[2];
    const float* mat   = (const float*)d_in[3];

    cudaFuncSetAttribute(gemm1, cudaFuncAttributeMaxDynamicSharedMemorySize, SMEM_BYTES);
    cudaFuncSetAttribute(gemm2, cudaFuncAttributeMaxDynamicSharedMemorySize, SMEM_BYTES);

    prep_all<<<(PREP_TOTAL + 255) / 256, 256>>>(mat, roles);
    gemm1<<<dim3(BSn / BM, 2), 256, SMEM_BYTES>>>(pre, wid);
    gemm2<<<dim3(BSn / BM, 3), 256, SMEM_BYTES>>>((float*)d_out);
}

// round 7
// speedup vs baseline: 1.1104x; 1.0352x over previous
#include <cuda_runtime.h>
#include <cuda_fp16.h>
#include <cstdint>

#define DEVINL __device__ __forceinline__

namespace {
constexpr int Sn  = 1024;
constexpr int Vn  = 300;
constexpr int PRE = 300;
constexpr int FLG = 16;
constexpr int KQn = 316;
constexpr int RD  = 200;
constexpr int BSn = 32768;            // B*S

// block 128 rows; warp grid 4x2, warp tile 32x56; K chunk 32; smem row stride 48 halves
constexpr int BM = 128, STR = 48;

// persistent proj buffer: 128 rows x 240 halves (224 used), hi+lo
constexpr int PSTRH = 240;                       // halves per row
constexpr int PSTRB = PSTRH * 2;                 // 480 bytes (== 96 mod 128)
constexpr int P_HI  = 0;
constexpr int P_LO  = BM * PSTRB;                // 61440
// A stages (phase 1 input tiles): 2 stages x (hi 12288 + lo 12288)
constexpr int A_OFF   = 2 * BM * PSTRB;          // 122880
constexpr int A_STAGE = 2 * BM * STR * 2;        // 24576
constexpr int A_LOOFF = BM * STR * 2;            // 12288
// B stages (phase1 mat / phase2 roles): 2 stages x (hi 10752 + lo 10752)
constexpr int B_OFF   = A_OFF + 2 * A_STAGE;     // 172032
constexpr int B_STAGE = 2 * 112 * STR * 2;       // 21504
constexpr int B_LOOFF = 112 * STR * 2;           // 10752
constexpr int SMEM_TOTAL = B_OFF + 2 * B_STAGE;  // 215040

constexpr int NC1 = 10;   // phase-1 K chunks (316 -> 320)
constexpr int NC2 = 7;    // phase-2 K chunks (200 -> 224)
constexpr int RW  = 224;  // roles padded k
constexpr int RV  = 336;  // roles padded v

constexpr int PREP_MAT_N  = 224 * 80;             // 17920
constexpr int PREP_ROLE_N = 32 * RV * (RW / 4);   // 602112
constexpr int PREP_TOTAL  = PREP_MAT_N + PREP_ROLE_N;
}

// fp16 hi/lo global scratch (allocation-free rule)
__device__ __half g_mh[224 * 320];
__device__ __half g_ml[224 * 320];
__device__ __half g_rh[(size_t)32 * RV * RW];
__device__ __half g_rl[(size_t)32 * RV * RW];

// ---------------------------------------------------------------------------
DEVINL uint32_t smem_u32(const void* p) {
    uint32_t a;
    asm("{ .reg .u64 t; cvta.to.shared.u64 t, %1; cvt.u32.u64 %0, t; }"
        : "=r"(a) : "l"(p));
    return a;
}
DEVINL void cp16(uint32_t dst, const void* src) {
    asm volatile("cp.async.cg.shared.global [%0], [%1], 16;"
                 :: "r"(dst), "l"(src) : "memory");
}
DEVINL void cp_commit() { asm volatile("cp.async.commit_group;" ::: "memory"); }
DEVINL void cp_wait0()  { asm volatile("cp.async.wait_group 0;" ::: "memory"); }

DEVINL void ldsm4(uint32_t a, uint32_t& r0, uint32_t& r1, uint32_t& r2, uint32_t& r3) {
    asm volatile("ldmatrix.sync.aligned.m8n8.x4.shared.b16 {%0,%1,%2,%3}, [%4];"
                 : "=r"(r0), "=r"(r1), "=r"(r2), "=r"(r3) : "r"(a));
}
DEVINL void ldsm2(uint32_t a, uint32_t& r0, uint32_t& r1) {
    asm volatile("ldmatrix.sync.aligned.m8n8.x2.shared.b16 {%0,%1}, [%2];"
                 : "=r"(r0), "=r"(r1) : "r"(a));
}
DEVINL void mma16816(float* c, const uint32_t* a, uint32_t b0, uint32_t b1) {
    asm volatile(
        "mma.sync.aligned.m16n8k16.row.col.f32.f16.f16.f32 "
        "{%0,%1,%2,%3}, {%4,%5,%6,%7}, {%8,%9}, {%0,%1,%2,%3};"
        : "+f"(c[0]), "+f"(c[1]), "+f"(c[2]), "+f"(c[3])
        : "r"(a[0]), "r"(a[1]), "r"(a[2]), "r"(a[3]), "r"(b0), "r"(b1));
}

// swizzle: flip 16B unit on (row & 4); valid for any row stride == 96 mod 128
DEVINL uint32_t swz(uint32_t byteoff, int row) { return byteoff ^ ((row & 4) << 2); }

DEVINL uint32_t packh(__half x, __half y) {
    return ((uint32_t)__half_as_ushort(y) << 16) | (uint32_t)__half_as_ushort(x);
}
DEVINL void split2h(float x, float y, uint32_t& hi, uint32_t& lo) {
    __half hx = __float2half_rn(x), hy = __float2half_rn(y);
    __half lx = __float2half_rn(x - __half2float(hx));
    __half ly = __float2half_rn(y - __half2float(hy));
    hi = packh(hx, hy);
    lo = packh(lx, ly);
}
DEVINL void sts2(uint32_t addr, uint32_t a, uint32_t b) {
    asm volatile("st.shared.v2.u32 [%0], {%1,%2};" :: "r"(addr), "r"(a), "r"(b) : "memory");
}
DEVINL void sts1(uint32_t addr, uint32_t a) {
    asm volatile("st.shared.b32 [%0], %1;" :: "r"(addr), "r"(a) : "memory");
}

// ---------------------------------------------------------------------------
// R3-proven compute: one K-chunk (2 x k16), warp tile 32x56, B via ldsm2
// aB/bB: smem byte addresses of the HI regions for this stage
// ---------------------------------------------------------------------------
DEVINL void compute_chunk(uint32_t aB, uint32_t bB, int lane, int wm, int wn,
                          float c[2][7][4]) {
    const int lr = lane & 15;
#pragma unroll
    for (int s = 0; s < 2; ++s) {
        uint32_t ah[2][4], al[2][4];
#pragma unroll
        for (int mi = 0; mi < 2; ++mi) {
            const int row = wm * 32 + mi * 16 + lr;
            const int col = s * 16 + (lane >> 4) * 8;
            const uint32_t off = swz((uint32_t)(row * 96 + col * 2), row);
            ldsm4(aB + off,            ah[mi][0], ah[mi][1], ah[mi][2], ah[mi][3]);
            ldsm4(aB + A_LOOFF + off,  al[mi][0], al[mi][1], al[mi][2], al[mi][3]);
        }
#pragma unroll
        for (int ni = 0; ni < 7; ++ni) {
            const int brow = wn * 56 + ni * 8 + (lr & 7);
            const int bcol = s * 16 + ((lr >> 3) & 1) * 8;
            const uint32_t boff = swz((uint32_t)(brow * 96 + bcol * 2), brow);
            uint32_t bh0, bh1, bl0, bl1;
            ldsm2(bB + boff,           bh0, bh1);
            ldsm2(bB + B_LOOFF + boff, bl0, bl1);
#pragma unroll
            for (int mi = 0; mi < 2; ++mi) {
                mma16816(c[mi][ni], ah[mi], bh0, bh1);
                mma16816(c[mi][ni], ah[mi], bl0, bl1);
                mma16816(c[mi][ni], al[mi], bh0, bh1);
            }
        }
    }
}

// phase-2 variant: A frags from the persistent proj buffer (row stride 480 B)
DEVINL void compute_chunk_p2(uint32_t pB, int kh0, uint32_t bB, int lane,
                             int wm, int wn, int scnt, float c[2][7][4]) {
    const int lr = lane & 15;
    for (int s = 0; s < scnt; ++s) {
        uint32_t ah[2][4], al[2][4];
#pragma unroll
        for (int mi = 0; mi < 2; ++mi) {
            const int row = wm * 32 + mi * 16 + lr;
            const int col = kh0 + s * 16 + (lane >> 4) * 8;
            const uint32_t off = swz((uint32_t)(row * PSTRB + col * 2), row);
            ldsm4(pB + off,                    ah[mi][0], ah[mi][1], ah[mi][2], ah[mi][3]);
            ldsm4(pB + (P_LO - P_HI) + off,    al[mi][0], al[mi][1], al[mi][2], al[mi][3]);
        }
#pragma unroll
        for (int ni = 0; ni < 7; ++ni) {
            const int brow = wn * 56 + ni * 8 + (lr & 7);
            const int bcol = s * 16 + ((lr >> 3) & 1) * 8;
            const uint32_t boff = swz((uint32_t)(brow * 96 + bcol * 2), brow);
            uint32_t bh0, bh1, bl0, bl1;
            ldsm2(bB + boff,           bh0, bh1);
            ldsm2(bB + B_LOOFF + boff, bl0, bl1);
#pragma unroll
            for (int mi = 0; mi < 2; ++mi) {
                mma16816(c[mi][ni], ah[mi], bh0, bh1);
                mma16816(c[mi][ni], ah[mi], bl0, bl1);
                mma16816(c[mi][ni], al[mi], bh0, bh1);
            }
        }
    }
}

// ===========================================================================
// prep (merged): split/pad matrix (transposed) and roles into fp16 hi/lo
// ===========================================================================
__global__ void prep_all(const float* __restrict__ mat,
                         const float* __restrict__ roles) {
    const int idx = blockIdx.x * 256 + threadIdx.x;
    if (idx < PREP_MAT_N) {
        const int n = idx / 80, k4 = (idx % 80) * 4;
#pragma unroll
        for (int i = 0; i < 4; ++i) {
            const int k = k4 + i;
            float v = 0.f;
            if (n < RD && k < KQn) v = mat[(size_t)k * RD + n];
            __half h = __float2half_rn(v);
            __half l = __float2half_rn(v - __half2float(h));
            g_mh[n * 320 + k] = h;
            g_ml[n * 320 + k] = l;
        }
    } else if (idx < PREP_TOTAL) {
        const int r0 = idx - PREP_MAT_N;
        const int b  = r0 / (RV * (RW / 4));
        const int r  = r0 % (RV * (RW / 4));
        const int v  = r / (RW / 4);
        const int k  = (r % (RW / 4)) * 4;
        uint32_t h0 = 0, l0 = 0, h1 = 0, l1 = 0;
        if (v < Vn && k < RD) {
            const float4 f = *(const float4*)(roles + ((size_t)b * Vn + v) * RD + k);
            split2h(f.x, f.y, h0, l0);
            split2h(f.z, f.w, h1, l1);
        }
        const size_t off = (size_t)b * RV * RW + (size_t)v * RW + k;
        *reinterpret_cast<uint2*>(g_rh + off) = make_uint2(h0, h1);
        *reinterpret_cast<uint2*>(g_rl + off) = make_uint2(l0, l1);
    }
}

// ===========================================================================
// fused: phase 1 builds proj[128,224] (hi/lo f16) in smem; phase 2 scores
// ===========================================================================
__global__ __launch_bounds__(256, 1) void fused(
    const float* __restrict__ pre,
    const float* __restrict__ wid,
    float* __restrict__ out)
{
    extern __shared__ __align__(128) char smraw[];
    const uint32_t sb = smem_u32(smraw);
    const int t = threadIdx.x, lane = t & 31, warp = t >> 5;
    const int wm = warp >> 1, wn = warp & 1;
    const int m0 = blockIdx.x * BM;
    const int b  = blockIdx.x >> 3;           // 8 m-tiles per batch

    float c[2][7][4];
    float4 ar[4];

    // ---------------- phase 1: proj ----------------
    auto ldA = [&](int ch) {
#pragma unroll
        for (int j = 0; j < 4; ++j) {
            const int idx = t + 256 * j;
            const int row = idx >> 3, c4 = idx & 7;
            const int kg = ch * 32 + c4 * 4;
            const size_t rg = (size_t)(m0 + row);
            float4 v = make_float4(0.f, 0.f, 0.f, 0.f);
            if (kg < PRE)      v = *(const float4*)(pre + rg * PRE + kg);
            else if (kg < KQn) v = *(const float4*)(wid + rg * FLG + (kg - PRE));
            ar[j] = v;
        }
    };
    auto stA = [&](uint32_t aB) {
#pragma unroll
        for (int j = 0; j < 4; ++j) {
            const int idx = t + 256 * j;
            const int row = idx >> 3, c4 = idx & 7;
            uint32_t h0, l0, h1, l1;
            split2h(ar[j].x, ar[j].y, h0, l0);
            split2h(ar[j].z, ar[j].w, h1, l1);
            const uint32_t off = swz((uint32_t)(row * 96 + c4 * 8), row);
            sts2(aB + off,           h0, h1);
            sts2(aB + A_LOOFF + off, l0, l1);
        }
    };
    auto issueB1 = [&](int ch, int n0, uint32_t bB) {
#pragma unroll
        for (int j = 0; j < 4; ++j) {
            const int idx = t + 256 * j;
            if (idx < 896) {
                const int sp = idx / 448, rem = idx % 448;
                const int row = rem >> 2, c8 = rem & 3;
                const __half* src = (sp ? g_ml : g_mh)
                                  + (size_t)(n0 + row) * 320 + ch * 32 + c8 * 8;
                const uint32_t off = (sp ? B_LOOFF : 0u)
                                   + swz((uint32_t)(row * 96 + c8 * 16), row);
                cp16(bB + off, src);
            }
        }
    };

#pragma unroll 1
    for (int nh = 0; nh < 2; ++nh) {
        const int n0 = nh * 112;
#pragma unroll
        for (int mi = 0; mi < 2; ++mi)
#pragma unroll
        for (int ni = 0; ni < 7; ++ni)
#pragma unroll
        for (int q = 0; q < 4; ++q) c[mi][ni][q] = 0.f;

        ldA(0);
        issueB1(0, n0, sb + B_OFF);
        cp_commit();
        stA(sb + A_OFF);
        cp_wait0();
        __syncthreads();

        for (int ch = 0; ch < NC1; ++ch) {
            const uint32_t aCur = sb + A_OFF + (uint32_t)(ch & 1) * A_STAGE;
            const uint32_t bCur = sb + B_OFF + (uint32_t)(ch & 1) * B_STAGE;
            const uint32_t aNxt = sb + A_OFF + (uint32_t)((ch + 1) & 1) * A_STAGE;
            const uint32_t bNxt = sb + B_OFF + (uint32_t)((ch + 1) & 1) * B_STAGE;
            if (ch + 1 < NC1) { ldA(ch + 1); issueB1(ch + 1, n0, bNxt); cp_commit(); }
            compute_chunk(aCur, bCur, lane, wm, wn, c);
            if (ch + 1 < NC1) { stA(aNxt); cp_wait0(); }
            __syncthreads();
        }

        // epilogue: accumulators -> persistent proj buffer (split fp16)
#pragma unroll
        for (int mi = 0; mi < 2; ++mi)
#pragma unroll
        for (int ni = 0; ni < 7; ++ni) {
            const int r0   = wm * 32 + mi * 16 + (lane >> 2);
            const int colg = n0 + wn * 56 + ni * 8 + (lane & 3) * 2;
            uint32_t h0, l0, h1, l1;
            split2h(c[mi][ni][0], c[mi][ni][1], h0, l0);
            split2h(c[mi][ni][2], c[mi][ni][3], h1, l1);
            const uint32_t o0 = swz((uint32_t)(r0 * PSTRB + colg * 2), r0);
            const uint32_t o1 = swz((uint32_t)((r0 + 8) * PSTRB + colg * 2), r0 + 8);
            sts1(sb + P_HI + o0, h0);
            sts1(sb + P_LO + o0, l0);
            sts1(sb + P_HI + o1, h1);
            sts1(sb + P_LO + o1, l1);
        }
        __syncthreads();
    }

    // ---------------- phase 2: scores ----------------
    const size_t rbase = (size_t)b * RV * RW;
    auto issueB2 = [&](int ch, int v0, uint32_t bB) {
        const int k0 = ch * 32;
#pragma unroll
        for (int j = 0; j < 4; ++j) {
            const int idx = t + 256 * j;
            if (idx < 896) {
                const int sp = idx / 448, rem = idx % 448;
                const int row = rem >> 2, c8 = rem & 3;
                const __half* src = (sp ? g_rl : g_rh)
                                  + rbase + (size_t)(v0 + row) * RW + k0 + c8 * 8;
                const uint32_t off = (sp ? B_LOOFF : 0u)
                                   + swz((uint32_t)(row * 96 + c8 * 16), row);
                cp16(bB + off, src);
            }
        }
    };

#pragma unroll 1
    for (int vt = 0; vt < 3; ++vt) {
        const int v0 = vt * 112;
#pragma unroll
        for (int mi = 0; mi < 2; ++mi)
#pragma unroll
        for (int ni = 0; ni < 7; ++ni)
#pragma unroll
        for (int q = 0; q < 4; ++q) c[mi][ni][q] = 0.f;

        issueB2(0, v0, sb + B_OFF);
        cp_commit();
        cp_wait0();
        __syncthreads();

        for (int ch = 0; ch < NC2; ++ch) {
            const uint32_t bCur = sb + B_OFF + (uint32_t)(ch & 1) * B_STAGE;
            const uint32_t bNxt = sb + B_OFF + (uint32_t)((ch + 1) & 1) * B_STAGE;
            if (ch + 1 < NC2) { issueB2(ch + 1, v0, bNxt); cp_commit(); }
            const int scnt = (ch == NC2 - 1) ? 1 : 2;   // k 208..223 is all-zero pad
            compute_chunk_p2(sb + P_HI, ch * 32, bCur, lane, wm, wn, scnt, c);
            if (ch + 1 < NC2) cp_wait0();
            __syncthreads();
        }

        // epilogue: fp32 stores, zero global column 1
#pragma unroll
        for (int mi = 0; mi < 2; ++mi)
#pragma unroll
        for (int ni = 0; ni < 7; ++ni) {
            const int r0   = m0 + wm * 32 + mi * 16 + (lane >> 2);
            const int colg = v0 + wn * 56 + ni * 8 + (lane & 3) * 2;
            if (colg < Vn) {
                float a0 = c[mi][ni][0], a1 = c[mi][ni][1];
                float a2 = c[mi][ni][2], a3 = c[mi][ni][3];
                if (colg == 0) { a1 = 0.f; a3 = 0.f; }
                *(float2*)(out + (size_t)r0 * Vn + colg)       = make_float2(a0, a1);
                *(float2*)(out + (size_t)(r0 + 8) * Vn + colg) = make_float2(a2, a3);
            }
        }
    }
}

// ===========================================================================
// kernel_launch  (inputs: role_vectors, pretrained_emb, word_id_emb, matrix, seq_len)
// ===========================================================================
extern "C" void kernel_launch(void* const* d_in, const int* in_sizes, int n_in,
                              void* d_out, int out_size)
{
    const float* roles = (const float*)d_in[0];
    const float* pre   = (const float*)d_in[1];
    const float* wid   = (const float*)d_in[2];
    const float* mat   = (const float*)d_in[3];

    cudaFuncSetAttribute(fused, cudaFuncAttributeMaxDynamicSharedMemorySize, SMEM_TOTAL);

    prep_all<<<(PREP_TOTAL + 255) / 256, 256>>>(mat, roles);
    fused<<<BSn / BM, 256, SMEM_TOTAL>>>(pre, wid, (float*)d_out);
}

// round 9
// speedup vs baseline: 1.2397x; 1.1165x over previous
#include <cuda_runtime.h>
#include <cuda_fp16.h>
#include <cstdint>

#define DEVINL __device__ __forceinline__

namespace {
constexpr int Sn  = 1024;
constexpr int Vn  = 300;
constexpr int PRE = 300;
constexpr int FLG = 16;
constexpr int KQn = 316;
constexpr int RD  = 200;
constexpr int BSn = 32768;            // B*S

// block 128 rows x (NI*16) cols, 8 warps (4x2), warp tile 32x(NI*8), K chunk 32
constexpr int BM = 128, STR = 48;     // smem row stride in halves (96 B)
constexpr int ASZ = BM * STR;                 // 6144 halves per split
constexpr int BSZmax = 112 * STR;             // sized for NI=7
constexpr int AHo = 0, ALo = ASZ, BHo = 2 * ASZ, BLo = 2 * ASZ + BSZmax;
constexpr int A_LOOFF = ASZ * 2;              // bytes
constexpr int B_LOOFF = BSZmax * 2;           // bytes (10752, mult of 128)
constexpr int STAGE_H = 2 * ASZ + 2 * BSZmax; // 23040 halves
constexpr int STAGE_B = STAGE_H * 2;          // 46080 bytes
constexpr int SMEM_BYTES = 2 * STAGE_B;       // 92160

constexpr int NC1 = 10;   // GEMM1 K chunks (316 -> 320)
constexpr int NC2 = 7;    // GEMM2 K chunks (200 -> 208 effective; last chunk 1 s-step)
constexpr int PW  = 224;  // proj padded width (k)
constexpr int RW  = 224;  // roles padded k
constexpr int RV  = 336;  // roles padded v

constexpr int PREP_MAT_N  = 224 * 80;             // 17920
constexpr int PREP_ROLE_N = 32 * RV * (RW / 4);   // 602112
constexpr int PREP_TOTAL  = PREP_MAT_N + PREP_ROLE_N;
}

// fp16 hi/lo global scratch (allocation-free rule)
__device__ __half g_ph[(size_t)BSn * PW];
__device__ __half g_pl[(size_t)BSn * PW];
__device__ __half g_mh[224 * 320];
__device__ __half g_ml[224 * 320];
__device__ __half g_rh[(size_t)32 * RV * RW];
__device__ __half g_rl[(size_t)32 * RV * RW];

// ---------------------------------------------------------------------------
DEVINL uint32_t smem_u32(const void* p) {
    uint32_t a;
    asm("{ .reg .u64 t; cvta.to.shared.u64 t, %1; cvt.u32.u64 %0, t; }"
        : "=r"(a) : "l"(p));
    return a;
}
DEVINL void cp16(uint32_t dst, const void* src) {
    asm volatile("cp.async.cg.shared.global [%0], [%1], 16;"
                 :: "r"(dst), "l"(src) : "memory");
}
DEVINL void cp_commit() { asm volatile("cp.async.commit_group;" ::: "memory"); }
DEVINL void cp_wait0()  { asm volatile("cp.async.wait_group 0;" ::: "memory"); }

DEVINL void ldsm4(uint32_t a, uint32_t& r0, uint32_t& r1, uint32_t& r2, uint32_t& r3) {
    asm volatile("ldmatrix.sync.aligned.m8n8.x4.shared.b16 {%0,%1,%2,%3}, [%4];"
                 : "=r"(r0), "=r"(r1), "=r"(r2), "=r"(r3) : "r"(a));
}
DEVINL void mma16816(float* c, const uint32_t* a, uint32_t b0, uint32_t b1) {
    asm volatile(
        "mma.sync.aligned.m16n8k16.row.col.f32.f16.f16.f32 "
        "{%0,%1,%2,%3}, {%4,%5,%6,%7}, {%8,%9}, {%0,%1,%2,%3};"
        : "+f"(c[0]), "+f"(c[1]), "+f"(c[2]), "+f"(c[3])
        : "r"(a[0]), "r"(a[1]), "r"(a[2]), "r"(a[3]), "r"(b0), "r"(b1));
}

// swizzle: flip 16B unit on (row & 4); conflict-free for row stride == 96 mod 128
DEVINL uint32_t swz(uint32_t byteoff, int row) { return byteoff ^ ((row & 4) << 2); }

DEVINL uint32_t packh(__half x, __half y) {
    return ((uint32_t)__half_as_ushort(y) << 16) | (uint32_t)__half_as_ushort(x);
}
DEVINL void split2h(float x, float y, uint32_t& hi, uint32_t& lo) {
    __half hx = __float2half_rn(x), hy = __float2half_rn(y);
    __half lx = __float2half_rn(x - __half2float(hx));
    __half ly = __float2half_rn(y - __half2float(hy));
    hi = packh(hx, hy);
    lo = packh(lx, ly);
}
DEVINL void store_split_pair(__half* hp, __half* lp, size_t off, float x, float y) {
    uint32_t hi, lo;
    split2h(x, y, hi, lo);
    *reinterpret_cast<uint32_t*>(hp + off) = hi;
    *reinterpret_cast<uint32_t*>(lp + off) = lo;
}
DEVINL void sts2(uint32_t addr, uint32_t a, uint32_t b) {
    asm volatile("st.shared.v2.u32 [%0], {%1,%2};" :: "r"(addr), "r"(a), "r"(b) : "memory");
}

// ---------------------------------------------------------------------------
// compute one K-chunk: warp tile 32 x (NI*8), 3-term fp16 split
// B hi/lo fetched in ONE ldsm4: lanes 0-15 -> HI region, lanes 16-31 -> LO region
// ---------------------------------------------------------------------------
template<int NI>
DEVINL void compute_chunk(uint32_t aB, uint32_t bB, int lane, int wm, int wn,
                          float c[2][NI][4], int scnt) {
    const int lr = lane & 15;
    // lane-constant pieces of the B address
    const uint32_t bRegion = (lane & 16) ? (uint32_t)B_LOOFF : 0u;  // hi vs lo
    const int bColSel = ((lane >> 3) & 1) * 8;                      // k+0-7 vs k+8-15
    const int bRowLane = lane & 7;
    for (int s = 0; s < scnt; ++s) {
        uint32_t ah[2][4], al[2][4];
#pragma unroll
        for (int mi = 0; mi < 2; ++mi) {
            const int row = wm * 32 + mi * 16 + lr;
            const int col = s * 16 + (lane >> 4) * 8;
            const uint32_t off = swz((uint32_t)(row * 96 + col * 2), row);
            ldsm4(aB + off,           ah[mi][0], ah[mi][1], ah[mi][2], ah[mi][3]);
            ldsm4(aB + A_LOOFF + off, al[mi][0], al[mi][1], al[mi][2], al[mi][3]);
        }
#pragma unroll
        for (int ni = 0; ni < NI; ++ni) {
            const int brow = wn * (NI * 8) + ni * 8 + bRowLane;
            const int bcol = s * 16 + bColSel;
            const uint32_t boff = bRegion + swz((uint32_t)(brow * 96 + bcol * 2), brow);
            uint32_t bh0, bh1, bl0, bl1;
            ldsm4(bB + boff, bh0, bh1, bl0, bl1);
#pragma unroll
            for (int mi = 0; mi < 2; ++mi) {
                mma16816(c[mi][ni], ah[mi], bh0, bh1);
                mma16816(c[mi][ni], ah[mi], bl0, bl1);
                mma16816(c[mi][ni], al[mi], bh0, bh1);
            }
        }
    }
}

// ===========================================================================
// prep (merged): split/pad matrix (transposed) and roles into fp16 hi/lo
// ===========================================================================
__global__ void prep_all(const float* __restrict__ mat,
                         const float* __restrict__ roles) {
    const int idx = blockIdx.x * 256 + threadIdx.x;
    if (idx < PREP_MAT_N) {
        const int n = idx / 80, k4 = (idx % 80) * 4;
#pragma unroll
        for (int i = 0; i < 4; ++i) {
            const int k = k4 + i;
            float v = 0.f;
            if (n < RD && k < KQn) v = mat[(size_t)k * RD + n];
            __half h = __float2half_rn(v);
            __half l = __float2half_rn(v - __half2float(h));
            g_mh[n * 320 + k] = h;
            g_ml[n * 320 + k] = l;
        }
    } else if (idx < PREP_TOTAL) {
        const int r0 = idx - PREP_MAT_N;
        const int b  = r0 / (RV * (RW / 4));
        const int r  = r0 % (RV * (RW / 4));
        const int v  = r / (RW / 4);
        const int k  = (r % (RW / 4)) * 4;
        uint32_t h0 = 0, l0 = 0, h1 = 0, l1 = 0;
        if (v < Vn && k < RD) {
            const float4 f = *(const float4*)(roles + ((size_t)b * Vn + v) * RD + k);
            split2h(f.x, f.y, h0, l0);
            split2h(f.z, f.w, h1, l1);
        }
        const size_t off = (size_t)b * RV * RW + (size_t)v * RW + k;
        *reinterpret_cast<uint2*>(g_rh + off) = make_uint2(h0, h1);
        *reinterpret_cast<uint2*>(g_rl + off) = make_uint2(l0, l1);
    }
}

// ===========================================================================
// GEMM1 body: proj(hi/lo f16)[BS, n0..n0+NI*16) = concat(pre,wid) @ mat
// ===========================================================================
template<int NI>
DEVINL void gemm1_body(const float* __restrict__ pre,
                       const float* __restrict__ wid,
                       uint32_t sb0, int m0, int n0,
                       int t, int lane, int wm, int wn) {
    float c[2][NI][4] = {};
    float4 ar[4];

    auto ldA = [&](int ch) {
#pragma unroll
        for (int j = 0; j < 4; ++j) {
            const int idx = t + 256 * j;
            const int row = idx >> 3, c4 = idx & 7;
            const int kg = ch * 32 + c4 * 4;
            const size_t rg = (size_t)(m0 + row);
            float4 v = make_float4(0.f, 0.f, 0.f, 0.f);
            if (kg < PRE)      v = *(const float4*)(pre + rg * PRE + kg);
            else if (kg < KQn) v = *(const float4*)(wid + rg * FLG + (kg - PRE));
            ar[j] = v;
        }
    };
    auto stA = [&](uint32_t sb) {
#pragma unroll
        for (int j = 0; j < 4; ++j) {
            const int idx = t + 256 * j;
            const int row = idx >> 3, c4 = idx & 7;
            uint32_t h0, l0, h1, l1;
            split2h(ar[j].x, ar[j].y, h0, l0);
            split2h(ar[j].z, ar[j].w, h1, l1);
            const uint32_t off = swz((uint32_t)(row * 96 + c4 * 8), row);
            sts2(sb + AHo * 2 + off, h0, h1);
            sts2(sb + ALo * 2 + off, l0, l1);
        }
    };
    auto issueB = [&](int ch, uint32_t sb) {
#pragma unroll
        for (int j = 0; j < 4; ++j) {
            const int idx = t + 256 * j;
            if (idx < NI * 128) {
                const int sp = idx / (NI * 64), rem = idx % (NI * 64);
                const int row = rem >> 2, c8 = rem & 3;
                const __half* src = (sp ? g_ml : g_mh)
                                  + (size_t)(n0 + row) * 320 + ch * 32 + c8 * 8;
                const uint32_t off = (sp ? BLo : BHo) * 2
                                   + swz((uint32_t)(row * 96 + c8 * 16), row);
                cp16(sb + off, src);
            }
        }
    };

    ldA(0);
    issueB(0, sb0);
    cp_commit();
    stA(sb0);
    cp_wait0();
    __syncthreads();

    for (int ch = 0; ch < NC1; ++ch) {
        const uint32_t cur = sb0 + (uint32_t)(ch & 1) * STAGE_B;
        const uint32_t nxt = sb0 + (uint32_t)((ch + 1) & 1) * STAGE_B;
        if (ch + 1 < NC1) { ldA(ch + 1); issueB(ch + 1, nxt); cp_commit(); }
        compute_chunk<NI>(cur + AHo * 2, cur + BHo * 2, lane, wm, wn, c, 2);
        if (ch + 1 < NC1) { stA(nxt); cp_wait0(); }
        __syncthreads();
    }

#pragma unroll
    for (int mi = 0; mi < 2; ++mi)
#pragma unroll
    for (int ni = 0; ni < NI; ++ni) {
        const int r0   = m0 + wm * 32 + mi * 16 + (lane >> 2);
        const int colg = n0 + wn * (NI * 8) + ni * 8 + (lane & 3) * 2;
        store_split_pair(g_ph, g_pl, (size_t)r0 * PW + colg,
                         c[mi][ni][0], c[mi][ni][1]);
        store_split_pair(g_ph, g_pl, (size_t)(r0 + 8) * PW + colg,
                         c[mi][ni][2], c[mi][ni][3]);
    }
}

__global__ __launch_bounds__(256, 2) void gemm1(
    const float* __restrict__ pre,
    const float* __restrict__ wid)
{
    extern __shared__ __align__(128) char smraw[];
    const uint32_t sb0 = smem_u32(smraw);
    const int t = threadIdx.x, lane = t & 31, warp = t >> 5;
    const int wm = warp >> 1, wn = warp & 1;
    const int m0 = blockIdx.x * BM;
    if (blockIdx.y == 0)
        gemm1_body<7>(pre, wid, sb0, m0, 0,   t, lane, wm, wn);   // cols 0..111
    else
        gemm1_body<6>(pre, wid, sb0, m0, 112, t, lane, wm, wn);   // cols 112..207
}

// ===========================================================================
// GEMM2 body: out[r, v0..) = proj[r,:208) . roles, col v==1 zeroed
// ===========================================================================
template<int NI>
DEVINL void gemm2_body(float* __restrict__ out,
                       uint32_t sb0, int m0, int v0, int b,
                       int t, int lane, int wm, int wn) {
    float c[2][NI][4] = {};
    const size_t rbase = (size_t)b * RV * RW;

    auto issue = [&](int ch, uint32_t sb) {
        const int k0 = ch * 32;
#pragma unroll
        for (int j = 0; j < 8; ++j) {
            const int idx = t + 256 * j;
            if (idx < 1024) {                       // A: proj hi/lo
                const int sp = idx >> 9, rem = idx & 511;
                const int row = rem >> 2, c8 = rem & 3;
                const __half* src = (sp ? g_pl : g_ph)
                                  + (size_t)(m0 + row) * PW + k0 + c8 * 8;
                const uint32_t off = (sp ? ALo : AHo) * 2
                                   + swz((uint32_t)(row * 96 + c8 * 16), row);
                cp16(sb + off, src);
            } else if (idx < 1024 + NI * 128) {     // B: roles hi/lo
                const int i2 = idx - 1024;
                const int sp = i2 / (NI * 64), rem = i2 % (NI * 64);
                const int row = rem >> 2, c8 = rem & 3;
                const __half* src = (sp ? g_rl : g_rh)
                                  + rbase + (size_t)(v0 + row) * RW + k0 + c8 * 8;
                const uint32_t off = (sp ? BLo : BHo) * 2
                                   + swz((uint32_t)(row * 96 + c8 * 16), row);
                cp16(sb + off, src);
            }
        }
    };

    issue(0, sb0);
    cp_commit();
    cp_wait0();
    __syncthreads();

    for (int ch = 0; ch < NC2; ++ch) {
        const uint32_t cur = sb0 + (uint32_t)(ch & 1) * STAGE_B;
        const uint32_t nxt = sb0 + (uint32_t)((ch + 1) & 1) * STAGE_B;
        if (ch + 1 < NC2) { issue(ch + 1, nxt); cp_commit(); }
        const int scnt = (ch == NC2 - 1) ? 1 : 2;   // k 208..223 is all-zero pad
        compute_chunk<NI>(cur + AHo * 2, cur + BHo * 2, lane, wm, wn, c, scnt);
        if (ch + 1 < NC2) cp_wait0();
        __syncthreads();
    }

#pragma unroll
    for (int mi = 0; mi < 2; ++mi)
#pragma unroll
    for (int ni = 0; ni < NI; ++ni) {
        const int r0   = m0 + wm * 32 + mi * 16 + (lane >> 2);
        const int colg = v0 + wn * (NI * 8) + ni * 8 + (lane & 3) * 2;
        if (colg < Vn) {
            float a0 = c[mi][ni][0], a1 = c[mi][ni][1];
            float a2 = c[mi][ni][2], a3 = c[mi][ni][3];
            if (colg == 0) { a1 = 0.f; a3 = 0.f; }
            *(float2*)(out + (size_t)r0 * Vn + colg)       = make_float2(a0, a1);
            *(float2*)(out + (size_t)(r0 + 8) * Vn + colg) = make_float2(a2, a3);
        }
    }
}

__global__ __launch_bounds__(256, 2) void gemm2(float* __restrict__ out)
{
    extern __shared__ __align__(128) char smraw[];
    const uint32_t sb0 = smem_u32(smraw);
    const int t = threadIdx.x, lane = t & 31, warp = t >> 5;
    const int wm = warp >> 1, wn = warp & 1;
    const int m0 = blockIdx.x * BM;
    const int b  = blockIdx.x >> 3;           // 8 M-tiles per batch
    if (blockIdx.y < 2)
        gemm2_body<7>(out, sb0, m0, blockIdx.y * 112, b, t, lane, wm, wn);
    else
        gemm2_body<5>(out, sb0, m0, 224, b, t, lane, wm, wn);   // v 224..303
}

// ===========================================================================
// kernel_launch  (inputs: role_vectors, pretrained_emb, word_id_emb, matrix, seq_len)
// ===========================================================================
extern "C" void kernel_launch(void* const* d_in, const int* in_sizes, int n_in,
                              void* d_out, int out_size)
{
    const float* roles = (const float*)d_in[0];
    const float* pre   = (const float*)d_in[1];
    const float* wid   = (const float*)d_in[2];
    const float* mat   = (const float*)d_in[3];

    cudaFuncSetAttribute(gemm1, cudaFuncAttributeMaxDynamicSharedMemorySize, SMEM_BYTES);
    cudaFuncSetAttribute(gemm2, cudaFuncAttributeMaxDynamicSharedMemorySize, SMEM_BYTES);

    prep_all<<<(PREP_TOTAL + 255) / 256, 256>>>(mat, roles);
    gemm1<<<dim3(BSn / BM, 2), 256, SMEM_BYTES>>>(pre, wid);
    gemm2<<<dim3(BSn / BM, 3), 256, SMEM_BYTES>>>((float*)d_out);
}

// round 10
// speedup vs baseline: 2.3214x; 1.8725x over previous
#include <cuda_runtime.h>
#include <cuda_fp16.h>
#include <cstdint>

#define DEVINL __device__ __forceinline__

namespace {
constexpr int Sn  = 1024;
constexpr int Vn  = 300;
constexpr int PRE = 300;
constexpr int FLG = 16;
constexpr int KQn = 316;
constexpr int RD  = 200;
constexpr int BSn = 32768;            // B*S

// block 128 rows x (NI*16) cols, 8 warps (4x2), warp tile 32x(NI*8), K chunk 32
constexpr int BM = 128;
constexpr int A_STAGE = BM * 48 * 2;        // 12288 B (128 rows x 96B)
constexpr int B_STAGEB = 112 * 48 * 2;      // 10752 B (<=112 rows x 96B)
constexpr int STAGE_B  = A_STAGE + B_STAGEB; // 23040
constexpr int AHo = 0, BHo = A_STAGE;        // offsets within a stage
constexpr int NSTAGE = 3;
constexpr int SMEM_BYTES = NSTAGE * STAGE_B; // 69120

constexpr int NC1 = 10;   // GEMM1 K chunks (316 -> 320)
constexpr int NC2 = 7;    // GEMM2 K chunks (200 -> 224; last chunk 1 s-step)
constexpr int PW  = 224;  // proj padded width (k)
constexpr int RW  = 224;  // roles padded k
constexpr int RV  = 336;  // roles padded v

constexpr int PREP_MAT_N  = 224 * 80;             // 17920
constexpr int PREP_ROLE_N = 32 * RV * (RW / 4);   // 602112
constexpr int PREP_TOTAL  = PREP_MAT_N + PREP_ROLE_N;
}

// fp16 global scratch (allocation-free rule; zero-initialized .bss)
__device__ __half g_ph[(size_t)BSn * PW];     // proj (cols 208-223 stay zero)
__device__ __half g_mh[224 * 320];            // matrix, transposed+padded
__device__ __half g_rh[(size_t)32 * RV * RW]; // roles, padded

// ---------------------------------------------------------------------------
DEVINL uint32_t smem_u32(const void* p) {
    uint32_t a;
    asm("{ .reg .u64 t; cvta.to.shared.u64 t, %1; cvt.u32.u64 %0, t; }"
        : "=r"(a) : "l"(p));
    return a;
}
DEVINL void cp16(uint32_t dst, const void* src) {
    asm volatile("cp.async.cg.shared.global [%0], [%1], 16;"
                 :: "r"(dst), "l"(src) : "memory");
}
DEVINL void cp_commit() { asm volatile("cp.async.commit_group;" ::: "memory"); }
DEVINL void cp_wait0()  { asm volatile("cp.async.wait_group 0;" ::: "memory"); }
DEVINL void cp_wait1()  { asm volatile("cp.async.wait_group 1;" ::: "memory"); }

DEVINL void ldsm4(uint32_t a, uint32_t& r0, uint32_t& r1, uint32_t& r2, uint32_t& r3) {
    asm volatile("ldmatrix.sync.aligned.m8n8.x4.shared.b16 {%0,%1,%2,%3}, [%4];"
                 : "=r"(r0), "=r"(r1), "=r"(r2), "=r"(r3) : "r"(a));
}
DEVINL void mma16816(float* c, const uint32_t* a, uint32_t b0, uint32_t b1) {
    asm volatile(
        "mma.sync.aligned.m16n8k16.row.col.f32.f16.f16.f32 "
        "{%0,%1,%2,%3}, {%4,%5,%6,%7}, {%8,%9}, {%0,%1,%2,%3};"
        : "+f"(c[0]), "+f"(c[1]), "+f"(c[2]), "+f"(c[3])
        : "r"(a[0]), "r"(a[1]), "r"(a[2]), "r"(a[3]), "r"(b0), "r"(b1));
}

// swizzle: flip 16B unit on (row & 4); conflict-free for row stride == 96 mod 128
DEVINL uint32_t swz(uint32_t byteoff, int row) { return byteoff ^ ((row & 4) << 2); }

DEVINL uint32_t packh(__half x, __half y) {
    return ((uint32_t)__half_as_ushort(y) << 16) | (uint32_t)__half_as_ushort(x);
}
DEVINL uint32_t pack2(float x, float y) {
    return packh(__float2half_rn(x), __float2half_rn(y));
}
DEVINL void sts2(uint32_t addr, uint32_t a, uint32_t b) {
    asm volatile("st.shared.v2.u32 [%0], {%1,%2};" :: "r"(addr), "r"(a), "r"(b) : "memory");
}

// ---------------------------------------------------------------------------
// compute one K-chunk: warp tile 32 x (NI*8), pure fp16 (1 MMA per frag)
// B: ONE ldsm4 per ni covers BOTH s-steps (lanes 0-15 -> s0 cols, 16-31 -> s1)
// ---------------------------------------------------------------------------
template<int NI>
DEVINL void compute_chunk(uint32_t aB, uint32_t bB, int lane, int wm, int wn,
                          float c[2][NI][4], int scnt) {
    const int lr = lane & 15;
    uint32_t a[2][2][4];   // [s][mi]
#pragma unroll
    for (int s = 0; s < 2; ++s) if (s < scnt) {
#pragma unroll
        for (int mi = 0; mi < 2; ++mi) {
            const int row = wm * 32 + mi * 16 + lr;
            const int col = s * 16 + (lane >> 4) * 8;
            const uint32_t off = swz((uint32_t)(row * 96 + col * 2), row);
            ldsm4(aB + off, a[s][mi][0], a[s][mi][1], a[s][mi][2], a[s][mi][3]);
        }
    }
    const int bRowLane = lane & 7;
    const uint32_t bColB = (uint32_t)((lane >> 3) * 16);  // bytes: 0,16,32,48 = k0-7/k8-15 x s0/s1
#pragma unroll
    for (int ni = 0; ni < NI; ++ni) {
        const int brow = wn * (NI * 8) + ni * 8 + bRowLane;
        const uint32_t boff = swz((uint32_t)(brow * 96) + bColB, brow);
        uint32_t b[4];
        ldsm4(bB + boff, b[0], b[1], b[2], b[3]);
#pragma unroll
        for (int s = 0; s < 2; ++s) if (s < scnt) {
#pragma unroll
            for (int mi = 0; mi < 2; ++mi)
                mma16816(c[mi][ni], a[s][mi], b[2 * s], b[2 * s + 1]);
        }
    }
}

// ===========================================================================
// prep (merged): matrix (transposed+padded) and roles (padded) -> fp16
// ===========================================================================
__global__ void prep_all(const float* __restrict__ mat,
                         const float* __restrict__ roles) {
    const int idx = blockIdx.x * 256 + threadIdx.x;
    if (idx < PREP_MAT_N) {
        const int n = idx / 80, k4 = (idx % 80) * 4;
#pragma unroll
        for (int i = 0; i < 4; ++i) {
            const int k = k4 + i;
            float v = 0.f;
            if (n < RD && k < KQn) v = mat[(size_t)k * RD + n];
            g_mh[n * 320 + k] = __float2half_rn(v);
        }
    } else if (idx < PREP_TOTAL) {
        const int r0 = idx - PREP_MAT_N;
        const int b  = r0 / (RV * (RW / 4));
        const int r  = r0 % (RV * (RW / 4));
        const int v  = r / (RW / 4);
        const int k  = (r % (RW / 4)) * 4;
        uint32_t h0 = 0, h1 = 0;
        if (v < Vn && k < RD) {
            const float4 f = *(const float4*)(roles + ((size_t)b * Vn + v) * RD + k);
            h0 = pack2(f.x, f.y);
            h1 = pack2(f.z, f.w);
        }
        const size_t off = (size_t)b * RV * RW + (size_t)v * RW + k;
        *reinterpret_cast<uint2*>(g_rh + off) = make_uint2(h0, h1);
    }
}

// ===========================================================================
// GEMM1 body: proj(f16)[BS, n0..n0+NI*16) = concat(pre,wid) @ mat
// ===========================================================================
template<int NI>
DEVINL void gemm1_body(const float* __restrict__ pre,
                       const float* __restrict__ wid,
                       uint32_t sb0, int m0, int n0,
                       int t, int lane, int wm, int wn) {
    float c[2][NI][4] = {};
    float4 ar[4];

    auto st = [&](int i) { return sb0 + (uint32_t)i * STAGE_B; };

    auto ldA = [&](int ch) {
#pragma unroll
        for (int j = 0; j < 4; ++j) {
            const int idx = t + 256 * j;
            const int row = idx >> 3, c4 = idx & 7;
            const int kg = ch * 32 + c4 * 4;
            const size_t rg = (size_t)(m0 + row);
            float4 v = make_float4(0.f, 0.f, 0.f, 0.f);
            if (kg < PRE)      v = *(const float4*)(pre + rg * PRE + kg);
            else if (kg < KQn) v = *(const float4*)(wid + rg * FLG + (kg - PRE));
            ar[j] = v;
        }
    };
    auto stA = [&](uint32_t sb) {
#pragma unroll
        for (int j = 0; j < 4; ++j) {
            const int idx = t + 256 * j;
            const int row = idx >> 3, c4 = idx & 7;
            const uint32_t off = swz((uint32_t)(row * 96 + c4 * 8), row);
            sts2(sb + AHo + off, pack2(ar[j].x, ar[j].y), pack2(ar[j].z, ar[j].w));
        }
    };
    auto issueB = [&](int ch, uint32_t sb) {
#pragma unroll
        for (int j = 0; j < 2; ++j) {
            const int idx = t + 256 * j;
            if (idx < NI * 64) {
                const int row = idx >> 2, c16 = idx & 3;
                const __half* src = g_mh + (size_t)(n0 + row) * 320 + ch * 32 + c16 * 8;
                const uint32_t off = swz((uint32_t)(row * 96 + c16 * 16), row);
                cp16(sb + BHo + off, src);
            }
        }
    };

    ldA(0); issueB(0, st(0)); cp_commit(); stA(st(0));
    ldA(1); issueB(1, st(1)); cp_commit(); stA(st(1));

    for (int ch = 0; ch < NC1; ++ch) {
        if (ch + 1 < NC1) cp_wait1(); else cp_wait0();
        __syncthreads();
        const int pf = ch + 2;
        if (pf < NC1) { issueB(pf, st(pf % 3)); cp_commit(); ldA(pf); }
        const uint32_t cur = st(ch % 3);
        compute_chunk<NI>(cur + AHo, cur + BHo, lane, wm, wn, c, 2);
        if (pf < NC1) stA(st(pf % 3));
    }

    // epilogue: fp32 accum -> proj fp16
#pragma unroll
    for (int mi = 0; mi < 2; ++mi)
#pragma unroll
    for (int ni = 0; ni < NI; ++ni) {
        const int r0   = m0 + wm * 32 + mi * 16 + (lane >> 2);
        const int colg = n0 + wn * (NI * 8) + ni * 8 + (lane & 3) * 2;
        *reinterpret_cast<uint32_t*>(g_ph + (size_t)r0 * PW + colg)
            = pack2(c[mi][ni][0], c[mi][ni][1]);
        *reinterpret_cast<uint32_t*>(g_ph + (size_t)(r0 + 8) * PW + colg)
            = pack2(c[mi][ni][2], c[mi][ni][3]);
    }
}

__global__ __launch_bounds__(256, 2) void gemm1(
    const float* __restrict__ pre,
    const float* __restrict__ wid)
{
    extern __shared__ __align__(128) char smraw[];
    const uint32_t sb0 = smem_u32(smraw);
    const int t = threadIdx.x, lane = t & 31, warp = t >> 5;
    const int wm = warp >> 1, wn = warp & 1;
    const int m0 = blockIdx.x * BM;
    if (blockIdx.y == 0)
        gemm1_body<7>(pre, wid, sb0, m0, 0,   t, lane, wm, wn);   // cols 0..111
    else
        gemm1_body<6>(pre, wid, sb0, m0, 112, t, lane, wm, wn);   // cols 112..207
}

// ===========================================================================
// GEMM2 body: out[r, v0..) = proj[r,:208) . roles, col v==1 zeroed
// ===========================================================================
template<int NI>
DEVINL void gemm2_body(float* __restrict__ out,
                       uint32_t sb0, int m0, int v0, int b,
                       int t, int lane, int wm, int wn) {
    float c[2][NI][4] = {};
    const size_t rbase = (size_t)b * RV * RW;

    auto st = [&](int i) { return sb0 + (uint32_t)i * STAGE_B; };

    auto issue = [&](int ch, uint32_t sb) {
        const int k0 = ch * 32;
#pragma unroll
        for (int j = 0; j < 4; ++j) {
            const int idx = t + 256 * j;
            if (idx < 512) {                        // A: proj
                const int row = idx >> 2, c16 = idx & 3;
                const __half* src = g_ph + (size_t)(m0 + row) * PW + k0 + c16 * 8;
                const uint32_t off = swz((uint32_t)(row * 96 + c16 * 16), row);
                cp16(sb + AHo + off, src);
            } else if (idx < 512 + NI * 64) {       // B: roles
                const int i2 = idx - 512;
                const int row = i2 >> 2, c16 = i2 & 3;
                const __half* src = g_rh + rbase + (size_t)(v0 + row) * RW + k0 + c16 * 8;
                const uint32_t off = swz((uint32_t)(row * 96 + c16 * 16), row);
                cp16(sb + BHo + off, src);
            }
        }
    };

    issue(0, st(0)); cp_commit();
    issue(1, st(1)); cp_commit();

    for (int ch = 0; ch < NC2; ++ch) {
        if (ch + 1 < NC2) cp_wait1(); else cp_wait0();
        __syncthreads();
        const int pf = ch + 2;
        if (pf < NC2) { issue(pf, st(pf % 3)); cp_commit(); }
        const int scnt = (ch == NC2 - 1) ? 1 : 2;   // k 208..223 is all-zero pad
        const uint32_t cur = st(ch % 3);
        compute_chunk<NI>(cur + AHo, cur + BHo, lane, wm, wn, c, scnt);
    }

    // epilogue: fp32 stores, zero global column 1
#pragma unroll
    for (int mi = 0; mi < 2; ++mi)
#pragma unroll
    for (int ni = 0; ni < NI; ++ni) {
        const int r0   = m0 + wm * 32 + mi * 16 + (lane >> 2);
        const int colg = v0 + wn * (NI * 8) + ni * 8 + (lane & 3) * 2;
        if (colg < Vn) {
            float a0 = c[mi][ni][0], a1 = c[mi][ni][1];
            float a2 = c[mi][ni][2], a3 = c[mi][ni][3];
            if (colg == 0) { a1 = 0.f; a3 = 0.f; }
            *(float2*)(out + (size_t)r0 * Vn + colg)       = make_float2(a0, a1);
            *(float2*)(out + (size_t)(r0 + 8) * Vn + colg) = make_float2(a2, a3);
        }
    }
}

__global__ __launch_bounds__(256, 2) void gemm2(float* __restrict__ out)
{
    extern __shared__ __align__(128) char smraw[];
    const uint32_t sb0 = smem_u32(smraw);
    const int t = threadIdx.x, lane = t & 31, warp = t >> 5;
    const int wm = warp >> 1, wn = warp & 1;
    const int m0 = blockIdx.x * BM;
    const int b  = blockIdx.x >> 3;           // 8 M-tiles per batch
    if (blockIdx.y < 2)
        gemm2_body<7>(out, sb0, m0, blockIdx.y * 112, b, t, lane, wm, wn);
    else
        gemm2_body<5>(out, sb0, m0, 224, b, t, lane, wm, wn);   // v 224..303
}

// ===========================================================================
// kernel_launch  (inputs: role_vectors, pretrained_emb, word_id_emb, matrix, seq_len)
// ===========================================================================
extern "C" void kernel_launch(void* const* d_in, const int* in_sizes, int n_in,
                              void* d_out, int out_size)
{
    const float* roles = (const float*)d_in[0];
    const float* pre   = (const float*)d_in[1];
    const float* wid   = (const float*)d_in[2];
    const float* mat   = (const float*)d_in[3];

    cudaFuncSetAttribute(gemm1, cudaFuncAttributeMaxDynamicSharedMemorySize, SMEM_BYTES);
    cudaFuncSetAttribute(gemm2, cudaFuncAttributeMaxDynamicSharedMemorySize, SMEM_BYTES);

    prep_all<<<(PREP_TOTAL + 255) / 256, 256>>>(mat, roles);
    gemm1<<<dim3(BSn / BM, 2), 256, SMEM_BYTES>>>(pre, wid);
    gemm2<<<dim3(BSn / BM, 3), 256, SMEM_BYTES>>>((float*)d_out);
}